// round 9
// baseline (speedup 1.0000x reference)
#include <cuda_runtime.h>
#include <cuda_fp16.h>
#include <math.h>
#include <stdint.h>

// ---------------------------------------------------------------------------
// Problem constants
// ---------------------------------------------------------------------------
#define NT   2048
#define DM   2048
#define NE   64
#define TOPK 4
#define FF   512
#define NS   2
#define SFF  2048
#define CAP  256
#define NP   (NT * TOPK)

// ---------------------------------------------------------------------------
// Device scratch
// ---------------------------------------------------------------------------
__device__ float  g_logits[NT * NE];
__device__ int    g_topk_idx[NP];
__device__ float  g_topk_w[NP];
__device__ int    g_tok_table[NE * CAP];
__device__ float  g_w_slot[NE * CAP];
__device__ int    g_counts[NE];
__device__ __half g_xh[NT * DM];
__device__ __half g_h [NE * CAP * FF];
__device__ __half g_hs[NS * NT * SFF];

// ---------------------------------------------------------------------------
// Helpers
// ---------------------------------------------------------------------------
__device__ __forceinline__ uint32_t smem_u32(const void* p) {
    uint32_t a;
    asm("{ .reg .u64 t; cvta.to.shared.u64 t, %1; cvt.u32.u64 %0, t; }" : "=r"(a) : "l"(p));
    return a;
}
__device__ __forceinline__ void ldsm4(uint32_t r[4], uint32_t a) {
    asm volatile("ldmatrix.sync.aligned.m8n8.x4.shared.b16 {%0,%1,%2,%3}, [%4];"
        : "=r"(r[0]), "=r"(r[1]), "=r"(r[2]), "=r"(r[3]) : "r"(a));
}
__device__ __forceinline__ void mma_f16(float c[4], const uint32_t a[4], const uint32_t b[2]) {
    asm volatile("mma.sync.aligned.m16n8k16.row.col.f32.f16.f16.f32 "
        "{%0,%1,%2,%3}, {%4,%5,%6,%7}, {%8,%9}, {%0,%1,%2,%3};"
        : "+f"(c[0]), "+f"(c[1]), "+f"(c[2]), "+f"(c[3])
        : "r"(a[0]), "r"(a[1]), "r"(a[2]), "r"(a[3]), "r"(b[0]), "r"(b[1]));
}
__device__ __forceinline__ uint32_t h2u(__half2 h) { return *(uint32_t*)&h; }

#define CP_ASYNC16(sa, gp) asm volatile("cp.async.cg.shared.global [%0], [%1], 16;" :: "r"(sa), "l"(gp) : "memory")
#define CP_COMMIT()        asm volatile("cp.async.commit_group;" ::: "memory")
#define CP_WAIT0()         asm volatile("cp.async.wait_group 0;" ::: "memory")

#define SST_B 144

__device__ __forceinline__ void cvt_storeBh(float4 v, char* hi, int r, int c4) {
    __half2 h0 = __floats2half2_rn(v.x, v.y);
    __half2 h1 = __floats2half2_rn(v.z, v.w);
    *(uint2*)(hi + (uint32_t)(r * SST_B + c4 * 2)) = make_uint2(h2u(h0), h2u(h1));
}
__device__ __forceinline__ float silu_f(float g) { return g / (1.f + expf(-g)); }

// Stage layouts (4-stage ring)
#define ABYTES 18432                     // 128 rows * 144B
#define BBYTES  9216                     // 64 rows * 144B
#define GU_STG (ABYTES + 2 * BBYTES)     // A | Bg | Bu = 36864
#define DN_STG (2 * ABYTES)              // A | B(128 rows) = 36864
#define S_STAGES 4
#define GU_SMEM (S_STAGES * GU_STG)      // 147456
#define DN_SMEM (S_STAGES * DN_STG)      // 147456

// Named barriers: FULL(s)=1+s (1..4), EMPTY(s)=5+s (5..8)
#define BAR_SYNC(id)   asm volatile("bar.sync %0, 512;"   :: "r"(id) : "memory")
#define BAR_ARRIVE(id) asm volatile("bar.arrive %0, 512;" :: "r"(id) : "memory")

// ===========================================================================
// 0) x -> fp16 (+ zero expert counts)
// ===========================================================================
__global__ __launch_bounds__(256)
void k_cvt_x(const float* __restrict__ x)
{
    if (blockIdx.x == 0 && threadIdx.x < NE) g_counts[threadIdx.x] = 0;
    int i = (blockIdx.x * 256 + threadIdx.x) * 4;
    float4 v = *(const float4*)(x + i);
    __half2 h0 = __floats2half2_rn(v.x, v.y);
    __half2 h1 = __floats2half2_rn(v.z, v.w);
    *(uint2*)(g_xh + i) = make_uint2(h2u(h0), h2u(h1));
}

// ===========================================================================
// 1) Router logits (SIMT fp32)
// ===========================================================================
#define RBM 64
#define RBK 16
__global__ __launch_bounds__(256)
void k_router_logits(const float* __restrict__ x, const float* __restrict__ rw)
{
    __shared__ __align__(16) float As[RBK][RBM];
    __shared__ __align__(16) float Bs[RBK][RBM];
    const int tid = threadIdx.x;
    const int t0  = blockIdx.x * RBM;
    const int lr  = tid >> 2, lk = (tid & 3) * 4;
    const int ty4 = (tid >> 4) * 4, tx4 = (tid & 15) * 4;
    float acc[4][4];
#pragma unroll
    for (int i = 0; i < 4; i++)
#pragma unroll
        for (int j = 0; j < 4; j++) acc[i][j] = 0.f;
    for (int kt = 0; kt < DM; kt += RBK) {
        float4 a = *(const float4*)(x + (size_t)(t0 + lr) * DM + kt + lk);
        As[lk+0][lr] = a.x; As[lk+1][lr] = a.y; As[lk+2][lr] = a.z; As[lk+3][lr] = a.w;
        float4 b = *(const float4*)(rw + (size_t)lr * DM + kt + lk);
        Bs[lk+0][lr] = b.x; Bs[lk+1][lr] = b.y; Bs[lk+2][lr] = b.z; Bs[lk+3][lr] = b.w;
        __syncthreads();
#pragma unroll
        for (int k = 0; k < RBK; k++) {
            float4 av = *(const float4*)&As[k][ty4];
            float4 bv = *(const float4*)&Bs[k][tx4];
            float a4[4] = {av.x, av.y, av.z, av.w};
            float b4[4] = {bv.x, bv.y, bv.z, bv.w};
#pragma unroll
            for (int i = 0; i < 4; i++)
#pragma unroll
                for (int j = 0; j < 4; j++) acc[i][j] += a4[i] * b4[j];
        }
        __syncthreads();
    }
#pragma unroll
    for (int i = 0; i < 4; i++)
#pragma unroll
        for (int j = 0; j < 4; j++)
            g_logits[(size_t)(t0 + ty4 + i) * NE + tx4 + j] = acc[i][j];
}

// ===========================================================================
// 2) Top-k (1 warp / token)
// ===========================================================================
__global__ void k_topk(const float* __restrict__ bias)
{
    const int n = blockIdx.x, lane = threadIdx.x;
    float l0 = g_logits[n * NE + lane];
    float l1 = g_logits[n * NE + 32 + lane];
    float s0 = l0 + bias[lane];
    float s1 = l1 + bias[32 + lane];
    int ch_idx[TOPK]; float ch_l[TOPK];
#pragma unroll
    for (int r = 0; r < TOPK; r++) {
        float v = s0; int idx = lane;
        if (s1 > v) { v = s1; idx = lane + 32; }
#pragma unroll
        for (int off = 16; off > 0; off >>= 1) {
            float ov = __shfl_xor_sync(0xffffffffu, v, off);
            int   oi = __shfl_xor_sync(0xffffffffu, idx, off);
            if (ov > v || (ov == v && oi < idx)) { v = ov; idx = oi; }
        }
        int owner = (idx < 32) ? idx : (idx - 32);
        float rawA = __shfl_sync(0xffffffffu, l0, owner);
        float rawB = __shfl_sync(0xffffffffu, l1, owner);
        ch_idx[r] = idx;
        ch_l[r]   = (idx < 32) ? rawA : rawB;
        if (lane == owner) { if (idx < 32) s0 = -INFINITY; else s1 = -INFINITY; }
    }
    if (lane == 0) {
        float m = ch_l[0];
#pragma unroll
        for (int r = 1; r < TOPK; r++) m = fmaxf(m, ch_l[r]);
        float w[TOPK], sum = 0.f;
#pragma unroll
        for (int r = 0; r < TOPK; r++) { w[r] = expf(ch_l[r] - m); sum += w[r]; }
        float inv = 1.f / sum;
#pragma unroll
        for (int r = 0; r < TOPK; r++) {
            g_topk_idx[n * TOPK + r] = ch_idx[r];
            g_topk_w[n * TOPK + r]   = w[r] * inv;
        }
    }
}

// ===========================================================================
// 3) Dispatch (atomic slots; order-free, no overflow in practice)
// ===========================================================================
__global__ __launch_bounds__(256)
void k_dispatch_atomic()
{
    int p = blockIdx.x * 256 + threadIdx.x;
    int e = g_topk_idx[p];
    int slot = atomicAdd(&g_counts[e], 1);
    if (slot < CAP) {
        g_tok_table[e * CAP + slot] = p >> 2;
        g_w_slot[e * CAP + slot]    = g_topk_w[p];
    }
}

__global__ void k_tail_fill()
{
    int e = blockIdx.x;
    int cnt = g_counts[e]; if (cnt > CAP) cnt = CAP;
    for (int i = cnt + threadIdx.x; i < CAP; i += 256) {
        g_tok_table[e * CAP + i] = 0;
        g_w_slot[e * CAP + i]    = 0.f;
    }
    if (threadIdx.x == 0) g_counts[e] = cnt;
}

// ===========================================================================
// Consumer compute cores
// ===========================================================================
// GU: 8 consumer warps on 128Mx64N; warp tile 32Mx32N
__device__ __forceinline__ void gu_cons(uint32_t ub,
    uint32_t offA0, uint32_t offA1, uint32_t offB,
    float ag[2][4][4], float au[2][4][4])
{
    const uint32_t uA = ub, uBg = ub + ABYTES, uBu = uBg + BBYTES;
#pragma unroll
    for (int ks = 0; ks < 4; ks++) {
        uint32_t kb = ks * 32;
        uint32_t ah[2][4], bg[8], bu[8];
        ldsm4(ah[0], uA + offA0 + kb); ldsm4(ah[1], uA + offA1 + kb);
        ldsm4(bg,     uBg + offB + kb); ldsm4(bg + 4, uBg + offB + 16 * SST_B + kb);
        ldsm4(bu,     uBu + offB + kb); ldsm4(bu + 4, uBu + offB + 16 * SST_B + kb);
#pragma unroll
        for (int mf = 0; mf < 2; mf++)
#pragma unroll
            for (int nf = 0; nf < 4; nf++) {
                mma_f16(ag[mf][nf], ah[mf], &bg[nf * 2]);
                mma_f16(au[mf][nf], ah[mf], &bu[nf * 2]);
            }
    }
}

// DN: 8 consumer warps on 128Mx128N; warp tile 32Mx64N
__device__ __forceinline__ void dn_cons(uint32_t ub,
    uint32_t offA0, uint32_t offA1, uint32_t offB,
    float ac[2][8][4])
{
    const uint32_t uA = ub, uB = ub + ABYTES;
#pragma unroll
    for (int ks = 0; ks < 4; ks++) {
        uint32_t kb = ks * 32;
        uint32_t ah[2][4], bh[16];
        ldsm4(ah[0], uA + offA0 + kb); ldsm4(ah[1], uA + offA1 + kb);
#pragma unroll
        for (int q = 0; q < 4; q++)
            ldsm4(bh + 4 * q, uB + offB + q * 16 * SST_B + kb);
#pragma unroll
        for (int mf = 0; mf < 2; mf++)
#pragma unroll
            for (int nf = 0; nf < 8; nf++)
                mma_f16(ac[mf][nf], ah[mf], &bh[nf * 2]);
    }
}

// ===========================================================================
// GU kernels (warp-specialized): warps 0-7 consumers, 8-15 producers
// ===========================================================================
__global__ __launch_bounds__(512)
void k_sh_gu(const float* __restrict__ sgw, const float* __restrict__ suw)
{
    extern __shared__ char sm[];
    const int tid = threadIdx.x, wid = tid >> 5, lane = tid & 31;
    const int t0 = blockIdx.x * 128, f0 = blockIdx.y * 64, s = blockIdx.z;
    uint32_t smb = smem_u32(sm);
    const int NIT = DM / 64;

    if (wid < 8) {
        const int wm = (wid >> 1) * 32, wn = (wid & 1) * 32;
        const uint32_t offA0 = (uint32_t)(wm + (lane & 15)) * SST_B + (lane >> 4) * 16;
        const uint32_t offA1 = offA0 + 16 * SST_B;
        const uint32_t offB  = (uint32_t)(wn + ((lane >> 4) << 3) + (lane & 7)) * SST_B
                             + ((lane >> 3) & 1) * 16;
        float ag[2][4][4] = {}, au[2][4][4] = {};
        for (int it = 0; it < NIT; it++) {
            int st = it & (S_STAGES - 1);
            BAR_SYNC(1 + st);
            gu_cons(smb + st * GU_STG, offA0, offA1, offB, ag, au);
            BAR_ARRIVE(5 + st);
        }
        const int rl = lane >> 2, cp2 = (lane & 3) * 2;
#pragma unroll
        for (int mf = 0; mf < 2; mf++)
#pragma unroll
            for (int nf = 0; nf < 4; nf++) {
                int row = t0 + wm + mf * 16 + rl;
                int col = f0 + wn + nf * 8 + cp2;
                __half* b0 = g_hs + ((size_t)s * NT + row) * SFF + col;
                *(__half2*)b0 = __floats2half2_rn(silu_f(ag[mf][nf][0]) * au[mf][nf][0],
                                                  silu_f(ag[mf][nf][1]) * au[mf][nf][1]);
                *(__half2*)(b0 + (size_t)8 * SFF) =
                                __floats2half2_rn(silu_f(ag[mf][nf][2]) * au[mf][nf][2],
                                                  silu_f(ag[mf][nf][3]) * au[mf][nf][3]);
            }
    } else {
        const int ptid = tid - 256;
        int arow[4], ac8[4]; uint32_t asmo[4];
#pragma unroll
        for (int j = 0; j < 4; j++) {
            int ia = ptid + j * 256;
            arow[j] = ia >> 3; ac8[j] = (ia & 7) << 3;
            asmo[j] = (uint32_t)(arow[j] * SST_B + ac8[j] * 2);
        }
        const __half* Asrc = g_xh + (size_t)t0 * DM;
        const float*  Gsrc = sgw + ((size_t)s * SFF + f0) * DM;
        const float*  Usrc = suw + ((size_t)s * SFF + f0) * DM;
        float4 vg[4], vu[4];
#pragma unroll
        for (int j = 0; j < 4; j++) {
            int ib = ptid + j * 256;
            vg[j] = *(const float4*)(Gsrc + (size_t)(ib >> 4) * DM + ((ib & 15) << 2));
            vu[j] = *(const float4*)(Usrc + (size_t)(ib >> 4) * DM + ((ib & 15) << 2));
        }
        for (int it = 0; it < NIT; it++) {
            int st = it & (S_STAGES - 1);
            if (it >= S_STAGES) BAR_SYNC(5 + st);
            uint32_t sA = smb + st * GU_STG;
            char* base = sm + st * GU_STG;
            char* Bg = base + ABYTES; char* Bu = Bg + BBYTES;
            int kt = it * 64;
#pragma unroll
            for (int j = 0; j < 4; j++)
                CP_ASYNC16(sA + asmo[j], Asrc + (size_t)arow[j] * DM + kt + ac8[j]);
            CP_COMMIT();
#pragma unroll
            for (int j = 0; j < 4; j++) {
                int ib = ptid + j * 256;
                cvt_storeBh(vg[j], Bg, ib >> 4, (ib & 15) << 2);
                cvt_storeBh(vu[j], Bu, ib >> 4, (ib & 15) << 2);
            }
            CP_WAIT0();
            BAR_ARRIVE(1 + st);
            if (it + 1 < NIT) {
                int kt2 = kt + 64;
#pragma unroll
                for (int j = 0; j < 4; j++) {
                    int ib = ptid + j * 256;
                    vg[j] = *(const float4*)(Gsrc + (size_t)(ib >> 4) * DM + kt2 + ((ib & 15) << 2));
                    vu[j] = *(const float4*)(Usrc + (size_t)(ib >> 4) * DM + kt2 + ((ib & 15) << 2));
                }
            }
        }
    }
}

__global__ __launch_bounds__(512)
void k_ex_gu(const float* __restrict__ gw, const float* __restrict__ uw)
{
    const int e = blockIdx.x;
    const int t0 = blockIdx.y * 128, f0 = blockIdx.z * 64;
    if (t0 >= g_counts[e]) return;

    extern __shared__ char sm[];
    __shared__ int toks[128];
    const int tid = threadIdx.x, wid = tid >> 5, lane = tid & 31;
    uint32_t smb = smem_u32(sm);
    const int NIT = DM / 64;

    if (tid < 128) toks[tid] = g_tok_table[e * CAP + t0 + tid];
    __syncthreads();

    if (wid < 8) {
        const int wm = (wid >> 1) * 32, wn = (wid & 1) * 32;
        const uint32_t offA0 = (uint32_t)(wm + (lane & 15)) * SST_B + (lane >> 4) * 16;
        const uint32_t offA1 = offA0 + 16 * SST_B;
        const uint32_t offB  = (uint32_t)(wn + ((lane >> 4) << 3) + (lane & 7)) * SST_B
                             + ((lane >> 3) & 1) * 16;
        float ag[2][4][4] = {}, au[2][4][4] = {};
        for (int it = 0; it < NIT; it++) {
            int st = it & (S_STAGES - 1);
            BAR_SYNC(1 + st);
            gu_cons(smb + st * GU_STG, offA0, offA1, offB, ag, au);
            BAR_ARRIVE(5 + st);
        }
        const int rl = lane >> 2, cp2 = (lane & 3) * 2;
#pragma unroll
        for (int mf = 0; mf < 2; mf++)
#pragma unroll
            for (int nf = 0; nf < 4; nf++) {
                int row = t0 + wm + mf * 16 + rl;
                int col = f0 + wn + nf * 8 + cp2;
                __half* b0 = g_h + ((size_t)e * CAP + row) * FF + col;
                *(__half2*)b0 = __floats2half2_rn(silu_f(ag[mf][nf][0]) * au[mf][nf][0],
                                                  silu_f(ag[mf][nf][1]) * au[mf][nf][1]);
                *(__half2*)(b0 + (size_t)8 * FF) =
                                __floats2half2_rn(silu_f(ag[mf][nf][2]) * au[mf][nf][2],
                                                  silu_f(ag[mf][nf][3]) * au[mf][nf][3]);
            }
    } else {
        const int ptid = tid - 256;
        int ac8[4]; uint32_t asmo[4]; const __half* agp[4];
#pragma unroll
        for (int j = 0; j < 4; j++) {
            int ia = ptid + j * 256;
            int arow = ia >> 3; ac8[j] = (ia & 7) << 3;
            asmo[j] = (uint32_t)(arow * SST_B + ac8[j] * 2);
            agp[j]  = g_xh + (size_t)toks[arow] * DM;
        }
        const float* Gsrc = gw + ((size_t)e * FF + f0) * DM;
        const float* Usrc = uw + ((size_t)e * FF + f0) * DM;
        float4 vg[4], vu[4];
#pragma unroll
        for (int j = 0; j < 4; j++) {
            int ib = ptid + j * 256;
            vg[j] = *(const float4*)(Gsrc + (size_t)(ib >> 4) * DM + ((ib & 15) << 2));
            vu[j] = *(const float4*)(Usrc + (size_t)(ib >> 4) * DM + ((ib & 15) << 2));
        }
        for (int it = 0; it < NIT; it++) {
            int st = it & (S_STAGES - 1);
            if (it >= S_STAGES) BAR_SYNC(5 + st);
            uint32_t sA = smb + st * GU_STG;
            char* base = sm + st * GU_STG;
            char* Bg = base + ABYTES; char* Bu = Bg + BBYTES;
            int kt = it * 64;
#pragma unroll
            for (int j = 0; j < 4; j++)
                CP_ASYNC16(sA + asmo[j], agp[j] + kt + ac8[j]);
            CP_COMMIT();
#pragma unroll
            for (int j = 0; j < 4; j++) {
                int ib = ptid + j * 256;
                cvt_storeBh(vg[j], Bg, ib >> 4, (ib & 15) << 2);
                cvt_storeBh(vu[j], Bu, ib >> 4, (ib & 15) << 2);
            }
            CP_WAIT0();
            BAR_ARRIVE(1 + st);
            if (it + 1 < NIT) {
                int kt2 = kt + 64;
#pragma unroll
                for (int j = 0; j < 4; j++) {
                    int ib = ptid + j * 256;
                    vg[j] = *(const float4*)(Gsrc + (size_t)(ib >> 4) * DM + kt2 + ((ib & 15) << 2));
                    vu[j] = *(const float4*)(Usrc + (size_t)(ib >> 4) * DM + kt2 + ((ib & 15) << 2));
                }
            }
        }
    }
}

// ===========================================================================
// DN kernels (warp-specialized), CTA 128Mx128N
// ===========================================================================
__global__ __launch_bounds__(512)
void k_sh_dn(const float* __restrict__ sdw, float* __restrict__ out)
{
    extern __shared__ char sm[];
    const int tid = threadIdx.x, wid = tid >> 5, lane = tid & 31;
    const int t0 = blockIdx.x * 128, d0 = blockIdx.y * 128;
    uint32_t smb = smem_u32(sm);
    const int NIT = 64;

    if (wid < 8) {
        const int wm = (wid >> 1) * 32, wn = (wid & 1) * 64;
        const uint32_t offA0 = (uint32_t)(wm + (lane & 15)) * SST_B + (lane >> 4) * 16;
        const uint32_t offA1 = offA0 + 16 * SST_B;
        const uint32_t offB  = (uint32_t)(wn + ((lane >> 4) << 3) + (lane & 7)) * SST_B
                             + ((lane >> 3) & 1) * 16;
        float ac[2][8][4] = {};
        for (int it = 0; it < NIT; it++) {
            int st = it & (S_STAGES - 1);
            BAR_SYNC(1 + st);
            dn_cons(smb + st * DN_STG, offA0, offA1, offB, ac);
            BAR_ARRIVE(5 + st);
        }
        const int rl = lane >> 2, cp2 = (lane & 3) * 2;
#pragma unroll
        for (int mf = 0; mf < 2; mf++)
#pragma unroll
            for (int nf = 0; nf < 8; nf++) {
                int row = t0 + wm + mf * 16 + rl;
                int col = d0 + wn + nf * 8 + cp2;
                float* b0 = out + (size_t)row * DM + col;
                *(float2*)b0 = make_float2(ac[mf][nf][0], ac[mf][nf][1]);
                *(float2*)(b0 + (size_t)8 * DM) = make_float2(ac[mf][nf][2], ac[mf][nf][3]);
            }
    } else {
        const int ptid = tid - 256;
        int arow[4], ac8[4]; uint32_t asmo[4];
#pragma unroll
        for (int j = 0; j < 4; j++) {
            int ia = ptid + j * 256;
            arow[j] = ia >> 3; ac8[j] = (ia & 7) << 3;
            asmo[j] = (uint32_t)(arow[j] * SST_B + ac8[j] * 2);
        }
        float4 vb[8];
#pragma unroll
        for (int j = 0; j < 8; j++) {
            int ib = ptid + j * 256;
            vb[j] = *(const float4*)(sdw + ((size_t)d0 + (ib >> 4)) * SFF + ((ib & 15) << 2));
        }
        for (int it = 0; it < NIT; it++) {
            int st = it & (S_STAGES - 1);
            if (it >= S_STAGES) BAR_SYNC(5 + st);
            uint32_t sA = smb + st * DN_STG;
            char* B = sm + st * DN_STG + ABYTES;
            int s2 = it >> 5, kt = (it & 31) * 64;
#pragma unroll
            for (int j = 0; j < 4; j++)
                CP_ASYNC16(sA + asmo[j],
                           g_hs + ((size_t)s2 * NT + t0 + arow[j]) * SFF + kt + ac8[j]);
            CP_COMMIT();
#pragma unroll
            for (int j = 0; j < 8; j++) {
                int ib = ptid + j * 256;
                cvt_storeBh(vb[j], B, ib >> 4, (ib & 15) << 2);
            }
            CP_WAIT0();
            BAR_ARRIVE(1 + st);
            if (it + 1 < NIT) {
                int s3 = (it + 1) >> 5, kt2 = ((it + 1) & 31) * 64;
#pragma unroll
                for (int j = 0; j < 8; j++) {
                    int ib = ptid + j * 256;
                    vb[j] = *(const float4*)(sdw + ((size_t)s3 * DM + d0 + (ib >> 4)) * SFF + kt2 + ((ib & 15) << 2));
                }
            }
        }
    }
}

// ---- expert down fused with weighted combine (atomicAdd onto out) ---------
__global__ __launch_bounds__(512)
void k_ex_dn(const float* __restrict__ dw, float* __restrict__ out)
{
    const int e = blockIdx.x;
    const int t0 = blockIdx.y * 128, d0 = blockIdx.z * 128;
    if (t0 >= g_counts[e]) return;

    extern __shared__ char sm[];
    const int tid = threadIdx.x, wid = tid >> 5, lane = tid & 31;
    uint32_t smb = smem_u32(sm);
    const int NIT = FF / 64;

    if (wid < 8) {
        const int wm = (wid >> 1) * 32, wn = (wid & 1) * 64;
        const uint32_t offA0 = (uint32_t)(wm + (lane & 15)) * SST_B + (lane >> 4) * 16;
        const uint32_t offA1 = offA0 + 16 * SST_B;
        const uint32_t offB  = (uint32_t)(wn + ((lane >> 4) << 3) + (lane & 7)) * SST_B
                             + ((lane >> 3) & 1) * 16;
        float ac[2][8][4] = {};
        for (int it = 0; it < NIT; it++) {
            int st = it & (S_STAGES - 1);
            BAR_SYNC(1 + st);
            dn_cons(smb + st * DN_STG, offA0, offA1, offB, ac);
            BAR_ARRIVE(5 + st);
        }
        const int rl = lane >> 2, cp2 = (lane & 3) * 2;
#pragma unroll
        for (int mf = 0; mf < 2; mf++) {
            int s0i = t0 + wm + mf * 16 + rl;
            int s1i = s0i + 8;
            float w0 = g_w_slot[e * CAP + s0i];
            float w1 = g_w_slot[e * CAP + s1i];
            int   k0 = g_tok_table[e * CAP + s0i];
            int   k1 = g_tok_table[e * CAP + s1i];
#pragma unroll
            for (int nf = 0; nf < 8; nf++) {
                int col = d0 + wn + nf * 8 + cp2;
                if (w0 != 0.f) {
                    float* p = out + (size_t)k0 * DM + col;
                    atomicAdd(p,     w0 * ac[mf][nf][0]);
                    atomicAdd(p + 1, w0 * ac[mf][nf][1]);
                }
                if (w1 != 0.f) {
                    float* p = out + (size_t)k1 * DM + col;
                    atomicAdd(p,     w1 * ac[mf][nf][2]);
                    atomicAdd(p + 1, w1 * ac[mf][nf][3]);
                }
            }
        }
    } else {
        const int ptid = tid - 256;
        int arow[4], ac8[4]; uint32_t asmo[4];
#pragma unroll
        for (int j = 0; j < 4; j++) {
            int ia = ptid + j * 256;
            arow[j] = ia >> 3; ac8[j] = (ia & 7) << 3;
            asmo[j] = (uint32_t)(arow[j] * SST_B + ac8[j] * 2);
        }
        const __half* Asrc = g_h + ((size_t)e * CAP + t0) * FF;
        const float*  Bsrc = dw  + ((size_t)e * DM + d0) * FF;
        float4 vb[8];
#pragma unroll
        for (int j = 0; j < 8; j++) {
            int ib = ptid + j * 256;
            vb[j] = *(const float4*)(Bsrc + (size_t)(ib >> 4) * FF + ((ib & 15) << 2));
        }
        for (int it = 0; it < NIT; it++) {
            int st = it & (S_STAGES - 1);
            if (it >= S_STAGES) BAR_SYNC(5 + st);
            uint32_t sA = smb + st * DN_STG;
            char* B = sm + st * DN_STG + ABYTES;
            int kt = it * 64;
#pragma unroll
            for (int j = 0; j < 4; j++)
                CP_ASYNC16(sA + asmo[j], Asrc + (size_t)arow[j] * FF + kt + ac8[j]);
            CP_COMMIT();
#pragma unroll
            for (int j = 0; j < 8; j++) {
                int ib = ptid + j * 256;
                cvt_storeBh(vb[j], B, ib >> 4, (ib & 15) << 2);
            }
            CP_WAIT0();
            BAR_ARRIVE(1 + st);
            if (it + 1 < NIT) {
                int kt2 = kt + 64;
#pragma unroll
                for (int j = 0; j < 8; j++) {
                    int ib = ptid + j * 256;
                    vb[j] = *(const float4*)(Bsrc + (size_t)(ib >> 4) * FF + kt2 + ((ib & 15) << 2));
                }
            }
        }
    }
}

// ===========================================================================
// Launch
// ===========================================================================
extern "C" void kernel_launch(void* const* d_in, const int* in_sizes, int n_in,
                              void* d_out, int out_size)
{
    const float* x      = (const float*)d_in[0];
    const float* rw     = (const float*)d_in[1];
    const float* rbias  = (const float*)d_in[2];
    const float* gate_w = (const float*)d_in[3];
    const float* up_w   = (const float*)d_in[4];
    const float* down_w = (const float*)d_in[5];
    const float* sg_w   = (const float*)d_in[6];
    const float* su_w   = (const float*)d_in[7];
    const float* sd_w   = (const float*)d_in[8];
    float* out = (float*)d_out;

    cudaFuncSetAttribute(k_sh_gu, cudaFuncAttributeMaxDynamicSharedMemorySize, GU_SMEM);
    cudaFuncSetAttribute(k_ex_gu, cudaFuncAttributeMaxDynamicSharedMemorySize, GU_SMEM);
    cudaFuncSetAttribute(k_sh_dn, cudaFuncAttributeMaxDynamicSharedMemorySize, DN_SMEM);
    cudaFuncSetAttribute(k_ex_dn, cudaFuncAttributeMaxDynamicSharedMemorySize, DN_SMEM);

    k_cvt_x<<<NT * DM / 1024, 256>>>(x);
    k_router_logits<<<NT / RBM, 256>>>(x, rw);
    k_topk<<<NT, 32>>>(rbias);
    k_dispatch_atomic<<<NP / 256, 256>>>();
    k_tail_fill<<<NE, 256>>>();

    k_ex_gu<<<dim3(NE, CAP / 128, FF / 64), 512, GU_SMEM>>>(gate_w, up_w);
    k_sh_gu<<<dim3(NT / 128, SFF / 64, NS), 512, GU_SMEM>>>(sg_w, su_w);

    k_sh_dn<<<dim3(NT / 128, DM / 128), 512, DN_SMEM>>>(sd_w, out);
    // must run after k_sh_dn (accumulates onto its output); same stream => ordered
    k_ex_dn<<<dim3(NE, CAP / 128, DM / 128), 512, DN_SMEM>>>(down_w, out);
}

// round 10
// speedup vs baseline: 1.1461x; 1.1461x over previous
#include <cuda_runtime.h>
#include <cuda_fp16.h>
#include <math.h>
#include <stdint.h>

// ---------------------------------------------------------------------------
// Problem constants
// ---------------------------------------------------------------------------
#define NT   2048
#define DM   2048
#define NE   64
#define TOPK 4
#define FF   512
#define NS   2
#define SFF  2048
#define CAP  256
#define NP   (NT * TOPK)

// ---------------------------------------------------------------------------
// Device scratch
// ---------------------------------------------------------------------------
__device__ float  g_logits[NT * NE];
__device__ int    g_topk_idx[NP];
__device__ float  g_topk_w[NP];
__device__ int    g_tok_table[NE * CAP];
__device__ float  g_w_slot[NE * CAP];
__device__ int    g_counts[NE];
__device__ __half g_xh[NT * DM];
__device__ __half g_h [NE * CAP * FF];
__device__ __half g_hs[NS * NT * SFF];

// ---------------------------------------------------------------------------
// Helpers
// ---------------------------------------------------------------------------
__device__ __forceinline__ uint32_t smem_u32(const void* p) {
    uint32_t a;
    asm("{ .reg .u64 t; cvta.to.shared.u64 t, %1; cvt.u32.u64 %0, t; }" : "=r"(a) : "l"(p));
    return a;
}
__device__ __forceinline__ void ldsm4(uint32_t r[4], uint32_t a) {
    asm volatile("ldmatrix.sync.aligned.m8n8.x4.shared.b16 {%0,%1,%2,%3}, [%4];"
        : "=r"(r[0]), "=r"(r[1]), "=r"(r[2]), "=r"(r[3]) : "r"(a));
}
__device__ __forceinline__ void mma_f16(float c[4], const uint32_t a[4], const uint32_t b[2]) {
    asm volatile("mma.sync.aligned.m16n8k16.row.col.f32.f16.f16.f32 "
        "{%0,%1,%2,%3}, {%4,%5,%6,%7}, {%8,%9}, {%0,%1,%2,%3};"
        : "+f"(c[0]), "+f"(c[1]), "+f"(c[2]), "+f"(c[3])
        : "r"(a[0]), "r"(a[1]), "r"(a[2]), "r"(a[3]), "r"(b[0]), "r"(b[1]));
}
__device__ __forceinline__ uint32_t h2u(__half2 h) { return *(uint32_t*)&h; }

#define SST_B 144

// B: fp32 -> fp16 single (round-to-nearest)
__device__ __forceinline__ void cvt_storeBh(float4 v, char* hi, int r, int c4) {
    __half2 h0 = __floats2half2_rn(v.x, v.y);
    __half2 h1 = __floats2half2_rn(v.z, v.w);
    *(uint2*)(hi + (uint32_t)(r * SST_B + c4 * 2)) = make_uint2(h2u(h0), h2u(h1));
}
__device__ __forceinline__ void copy_storeA(uint4 v, char* dst, int r, int c8) {
    *(uint4*)(dst + (uint32_t)(r * SST_B + c8 * 2)) = v;
}
__device__ __forceinline__ float silu_f(float g) { return g / (1.f + expf(-g)); }

// Stage layouts (3-stage ring)
#define ABYTES 18432                     // 128 rows * 144B
#define BBYTES  9216                     // 64 rows * 144B
#define GU_STG (ABYTES + 2 * BBYTES)     // A | Bg | Bu = 36864
#define DN_STG (2 * ABYTES)              // A | B(128 rows) = 36864
#define S_STAGES 3
#define GU_SMEM (S_STAGES * GU_STG)      // 110592
#define DN_SMEM (S_STAGES * DN_STG)      // 110592

// Named barriers: FULL(s)=1+s, EMPTY(s)=4+s
#define BAR_SYNC(id)   asm volatile("bar.sync %0, 512;"   :: "r"(id) : "memory")
#define BAR_ARRIVE(id) asm volatile("bar.arrive %0, 512;" :: "r"(id) : "memory")

// ===========================================================================
// 0) x -> fp16 (+ zero expert counts)
// ===========================================================================
__global__ __launch_bounds__(256)
void k_cvt_x(const float* __restrict__ x)
{
    if (blockIdx.x == 0 && threadIdx.x < NE) g_counts[threadIdx.x] = 0;
    int i = (blockIdx.x * 256 + threadIdx.x) * 4;
    float4 v = *(const float4*)(x + i);
    __half2 h0 = __floats2half2_rn(v.x, v.y);
    __half2 h1 = __floats2half2_rn(v.z, v.w);
    *(uint2*)(g_xh + i) = make_uint2(h2u(h0), h2u(h1));
}

// ===========================================================================
// 1) Router logits (SIMT fp32)
// ===========================================================================
#define RBM 64
#define RBK 16
__global__ __launch_bounds__(256)
void k_router_logits(const float* __restrict__ x, const float* __restrict__ rw)
{
    __shared__ __align__(16) float As[RBK][RBM];
    __shared__ __align__(16) float Bs[RBK][RBM];
    const int tid = threadIdx.x;
    const int t0  = blockIdx.x * RBM;
    const int lr  = tid >> 2, lk = (tid & 3) * 4;
    const int ty4 = (tid >> 4) * 4, tx4 = (tid & 15) * 4;
    float acc[4][4];
#pragma unroll
    for (int i = 0; i < 4; i++)
#pragma unroll
        for (int j = 0; j < 4; j++) acc[i][j] = 0.f;
    for (int kt = 0; kt < DM; kt += RBK) {
        float4 a = *(const float4*)(x + (size_t)(t0 + lr) * DM + kt + lk);
        As[lk+0][lr] = a.x; As[lk+1][lr] = a.y; As[lk+2][lr] = a.z; As[lk+3][lr] = a.w;
        float4 b = *(const float4*)(rw + (size_t)lr * DM + kt + lk);
        Bs[lk+0][lr] = b.x; Bs[lk+1][lr] = b.y; Bs[lk+2][lr] = b.z; Bs[lk+3][lr] = b.w;
        __syncthreads();
#pragma unroll
        for (int k = 0; k < RBK; k++) {
            float4 av = *(const float4*)&As[k][ty4];
            float4 bv = *(const float4*)&Bs[k][tx4];
            float a4[4] = {av.x, av.y, av.z, av.w};
            float b4[4] = {bv.x, bv.y, bv.z, bv.w};
#pragma unroll
            for (int i = 0; i < 4; i++)
#pragma unroll
                for (int j = 0; j < 4; j++) acc[i][j] += a4[i] * b4[j];
        }
        __syncthreads();
    }
#pragma unroll
    for (int i = 0; i < 4; i++)
#pragma unroll
        for (int j = 0; j < 4; j++)
            g_logits[(size_t)(t0 + ty4 + i) * NE + tx4 + j] = acc[i][j];
}

// ===========================================================================
// 2) Top-k (1 warp / token)
// ===========================================================================
__global__ void k_topk(const float* __restrict__ bias)
{
    const int n = blockIdx.x, lane = threadIdx.x;
    float l0 = g_logits[n * NE + lane];
    float l1 = g_logits[n * NE + 32 + lane];
    float s0 = l0 + bias[lane];
    float s1 = l1 + bias[32 + lane];
    int ch_idx[TOPK]; float ch_l[TOPK];
#pragma unroll
    for (int r = 0; r < TOPK; r++) {
        float v = s0; int idx = lane;
        if (s1 > v) { v = s1; idx = lane + 32; }
#pragma unroll
        for (int off = 16; off > 0; off >>= 1) {
            float ov = __shfl_xor_sync(0xffffffffu, v, off);
            int   oi = __shfl_xor_sync(0xffffffffu, idx, off);
            if (ov > v || (ov == v && oi < idx)) { v = ov; idx = oi; }
        }
        int owner = (idx < 32) ? idx : (idx - 32);
        float rawA = __shfl_sync(0xffffffffu, l0, owner);
        float rawB = __shfl_sync(0xffffffffu, l1, owner);
        ch_idx[r] = idx;
        ch_l[r]   = (idx < 32) ? rawA : rawB;
        if (lane == owner) { if (idx < 32) s0 = -INFINITY; else s1 = -INFINITY; }
    }
    if (lane == 0) {
        float m = ch_l[0];
#pragma unroll
        for (int r = 1; r < TOPK; r++) m = fmaxf(m, ch_l[r]);
        float w[TOPK], sum = 0.f;
#pragma unroll
        for (int r = 0; r < TOPK; r++) { w[r] = expf(ch_l[r] - m); sum += w[r]; }
        float inv = 1.f / sum;
#pragma unroll
        for (int r = 0; r < TOPK; r++) {
            g_topk_idx[n * TOPK + r] = ch_idx[r];
            g_topk_w[n * TOPK + r]   = w[r] * inv;
        }
    }
}

// ===========================================================================
// 3) Dispatch (atomic slots; order-free, no overflow in practice)
// ===========================================================================
__global__ __launch_bounds__(256)
void k_dispatch_atomic()
{
    int p = blockIdx.x * 256 + threadIdx.x;
    int e = g_topk_idx[p];
    int slot = atomicAdd(&g_counts[e], 1);
    if (slot < CAP) {
        g_tok_table[e * CAP + slot] = p >> 2;
        g_w_slot[e * CAP + slot]    = g_topk_w[p];
    }
}

__global__ void k_tail_fill()
{
    int e = blockIdx.x;
    int cnt = g_counts[e]; if (cnt > CAP) cnt = CAP;
    for (int i = cnt + threadIdx.x; i < CAP; i += 256) {
        g_tok_table[e * CAP + i] = 0;
        g_w_slot[e * CAP + i]    = 0.f;
    }
    if (threadIdx.x == 0) g_counts[e] = cnt;
}

// ===========================================================================
// Consumer compute cores (single fp16 term both sides)
// ===========================================================================
// GU: 8 consumer warps on 128Mx64N; warp tile 32Mx32N
__device__ __forceinline__ void gu_cons(uint32_t ub,
    uint32_t offA0, uint32_t offA1, uint32_t offB,
    float ag[2][4][4], float au[2][4][4])
{
    const uint32_t uA = ub, uBg = ub + ABYTES, uBu = uBg + BBYTES;
#pragma unroll
    for (int ks = 0; ks < 4; ks++) {
        uint32_t kb = ks * 32;
        uint32_t ah[2][4], bg[8], bu[8];
        ldsm4(ah[0], uA + offA0 + kb); ldsm4(ah[1], uA + offA1 + kb);
        ldsm4(bg,     uBg + offB + kb); ldsm4(bg + 4, uBg + offB + 16 * SST_B + kb);
        ldsm4(bu,     uBu + offB + kb); ldsm4(bu + 4, uBu + offB + 16 * SST_B + kb);
#pragma unroll
        for (int mf = 0; mf < 2; mf++)
#pragma unroll
            for (int nf = 0; nf < 4; nf++) {
                mma_f16(ag[mf][nf], ah[mf], &bg[nf * 2]);
                mma_f16(au[mf][nf], ah[mf], &bu[nf * 2]);
            }
    }
}

// DN: 8 consumer warps on 128Mx128N; warp tile 32Mx64N
__device__ __forceinline__ void dn_cons(uint32_t ub,
    uint32_t offA0, uint32_t offA1, uint32_t offB,
    float ac[2][8][4])
{
    const uint32_t uA = ub, uB = ub + ABYTES;
#pragma unroll
    for (int ks = 0; ks < 4; ks++) {
        uint32_t kb = ks * 32;
        uint32_t ah[2][4], bh[16];
        ldsm4(ah[0], uA + offA0 + kb); ldsm4(ah[1], uA + offA1 + kb);
#pragma unroll
        for (int q = 0; q < 4; q++)
            ldsm4(bh + 4 * q, uB + offB + q * 16 * SST_B + kb);
#pragma unroll
        for (int mf = 0; mf < 2; mf++)
#pragma unroll
            for (int nf = 0; nf < 8; nf++)
                mma_f16(ac[mf][nf], ah[mf], &bh[nf * 2]);
    }
}

// ===========================================================================
// GU kernels (warp-specialized): warps 0-7 consumers, 8-15 producers
// ===========================================================================
__global__ __launch_bounds__(512)
void k_sh_gu(const float* __restrict__ sgw, const float* __restrict__ suw)
{
    extern __shared__ char sm[];
    const int tid = threadIdx.x, wid = tid >> 5, lane = tid & 31;
    const int t0 = blockIdx.x * 128, f0 = blockIdx.y * 64, s = blockIdx.z;
    uint32_t smb = smem_u32(sm);
    const int NIT = DM / 64;

    if (wid < 8) {
        const int wm = (wid >> 1) * 32, wn = (wid & 1) * 32;
        const uint32_t offA0 = (uint32_t)(wm + (lane & 15)) * SST_B + (lane >> 4) * 16;
        const uint32_t offA1 = offA0 + 16 * SST_B;
        const uint32_t offB  = (uint32_t)(wn + ((lane >> 4) << 3) + (lane & 7)) * SST_B
                             + ((lane >> 3) & 1) * 16;
        float ag[2][4][4] = {}, au[2][4][4] = {};
        for (int it = 0; it < NIT; it++) {
            int st = it % S_STAGES;
            BAR_SYNC(1 + st);
            gu_cons(smb + st * GU_STG, offA0, offA1, offB, ag, au);
            BAR_ARRIVE(4 + st);
        }
        const int rl = lane >> 2, cp2 = (lane & 3) * 2;
#pragma unroll
        for (int mf = 0; mf < 2; mf++)
#pragma unroll
            for (int nf = 0; nf < 4; nf++) {
                int row = t0 + wm + mf * 16 + rl;
                int col = f0 + wn + nf * 8 + cp2;
                __half* b0 = g_hs + ((size_t)s * NT + row) * SFF + col;
                *(__half2*)b0 = __floats2half2_rn(silu_f(ag[mf][nf][0]) * au[mf][nf][0],
                                                  silu_f(ag[mf][nf][1]) * au[mf][nf][1]);
                *(__half2*)(b0 + (size_t)8 * SFF) =
                                __floats2half2_rn(silu_f(ag[mf][nf][2]) * au[mf][nf][2],
                                                  silu_f(ag[mf][nf][3]) * au[mf][nf][3]);
            }
    } else {
        const int ptid = tid - 256;
        const __half* Asrc = g_xh + (size_t)t0 * DM;
        const float*  Gsrc = sgw + ((size_t)s * SFF + f0) * DM;
        const float*  Usrc = suw + ((size_t)s * SFF + f0) * DM;
        uint4 va[4]; float4 vg[4], vu[4];
#pragma unroll
        for (int j = 0; j < 4; j++) {
            int ia = ptid + j * 256;
            va[j] = *(const uint4*)(Asrc + (size_t)(ia >> 3) * DM + ((ia & 7) << 3));
            vg[j] = *(const float4*)(Gsrc + (size_t)(ia >> 4) * DM + ((ia & 15) << 2));
            vu[j] = *(const float4*)(Usrc + (size_t)(ia >> 4) * DM + ((ia & 15) << 2));
        }
        for (int it = 0; it < NIT; it++) {
            int st = it % S_STAGES;
            if (it >= S_STAGES) BAR_SYNC(4 + st);
            char* base = sm + st * GU_STG;
            char* A = base; char* Bg = base + ABYTES; char* Bu = Bg + BBYTES;
#pragma unroll
            for (int j = 0; j < 4; j++) {
                int ia = ptid + j * 256;
                copy_storeA(va[j], A, ia >> 3, (ia & 7) << 3);
                cvt_storeBh(vg[j], Bg, ia >> 4, (ia & 15) << 2);
                cvt_storeBh(vu[j], Bu, ia >> 4, (ia & 15) << 2);
            }
            BAR_ARRIVE(1 + st);
            if (it + 1 < NIT) {
                int kt = (it + 1) * 64;
#pragma unroll
                for (int j = 0; j < 4; j++) {
                    int ia = ptid + j * 256;
                    va[j] = *(const uint4*)(Asrc + (size_t)(ia >> 3) * DM + kt + ((ia & 7) << 3));
                    vg[j] = *(const float4*)(Gsrc + (size_t)(ia >> 4) * DM + kt + ((ia & 15) << 2));
                    vu[j] = *(const float4*)(Usrc + (size_t)(ia >> 4) * DM + kt + ((ia & 15) << 2));
                }
            }
        }
    }
}

__global__ __launch_bounds__(512)
void k_ex_gu(const float* __restrict__ gw, const float* __restrict__ uw)
{
    const int e = blockIdx.x;
    const int t0 = blockIdx.y * 128, f0 = blockIdx.z * 64;
    if (t0 >= g_counts[e]) return;

    extern __shared__ char sm[];
    __shared__ int toks[128];
    const int tid = threadIdx.x, wid = tid >> 5, lane = tid & 31;
    uint32_t smb = smem_u32(sm);
    const int NIT = DM / 64;

    if (tid < 128) toks[tid] = g_tok_table[e * CAP + t0 + tid];
    __syncthreads();

    if (wid < 8) {
        const int wm = (wid >> 1) * 32, wn = (wid & 1) * 32;
        const uint32_t offA0 = (uint32_t)(wm + (lane & 15)) * SST_B + (lane >> 4) * 16;
        const uint32_t offA1 = offA0 + 16 * SST_B;
        const uint32_t offB  = (uint32_t)(wn + ((lane >> 4) << 3) + (lane & 7)) * SST_B
                             + ((lane >> 3) & 1) * 16;
        float ag[2][4][4] = {}, au[2][4][4] = {};
        for (int it = 0; it < NIT; it++) {
            int st = it % S_STAGES;
            BAR_SYNC(1 + st);
            gu_cons(smb + st * GU_STG, offA0, offA1, offB, ag, au);
            BAR_ARRIVE(4 + st);
        }
        const int rl = lane >> 2, cp2 = (lane & 3) * 2;
#pragma unroll
        for (int mf = 0; mf < 2; mf++)
#pragma unroll
            for (int nf = 0; nf < 4; nf++) {
                int row = t0 + wm + mf * 16 + rl;
                int col = f0 + wn + nf * 8 + cp2;
                __half* b0 = g_h + ((size_t)e * CAP + row) * FF + col;
                *(__half2*)b0 = __floats2half2_rn(silu_f(ag[mf][nf][0]) * au[mf][nf][0],
                                                  silu_f(ag[mf][nf][1]) * au[mf][nf][1]);
                *(__half2*)(b0 + (size_t)8 * FF) =
                                __floats2half2_rn(silu_f(ag[mf][nf][2]) * au[mf][nf][2],
                                                  silu_f(ag[mf][nf][3]) * au[mf][nf][3]);
            }
    } else {
        const int ptid = tid - 256;
        const float* Gsrc = gw + ((size_t)e * FF + f0) * DM;
        const float* Usrc = uw + ((size_t)e * FF + f0) * DM;
        uint4 va[4]; float4 vg[4], vu[4];
#pragma unroll
        for (int j = 0; j < 4; j++) {
            int ia = ptid + j * 256;
            va[j] = *(const uint4*)(g_xh + (size_t)toks[ia >> 3] * DM + ((ia & 7) << 3));
            vg[j] = *(const float4*)(Gsrc + (size_t)(ia >> 4) * DM + ((ia & 15) << 2));
            vu[j] = *(const float4*)(Usrc + (size_t)(ia >> 4) * DM + ((ia & 15) << 2));
        }
        for (int it = 0; it < NIT; it++) {
            int st = it % S_STAGES;
            if (it >= S_STAGES) BAR_SYNC(4 + st);
            char* base = sm + st * GU_STG;
            char* A = base; char* Bg = base + ABYTES; char* Bu = Bg + BBYTES;
#pragma unroll
            for (int j = 0; j < 4; j++) {
                int ia = ptid + j * 256;
                copy_storeA(va[j], A, ia >> 3, (ia & 7) << 3);
                cvt_storeBh(vg[j], Bg, ia >> 4, (ia & 15) << 2);
                cvt_storeBh(vu[j], Bu, ia >> 4, (ia & 15) << 2);
            }
            BAR_ARRIVE(1 + st);
            if (it + 1 < NIT) {
                int kt = (it + 1) * 64;
#pragma unroll
                for (int j = 0; j < 4; j++) {
                    int ia = ptid + j * 256;
                    va[j] = *(const uint4*)(g_xh + (size_t)toks[ia >> 3] * DM + kt + ((ia & 7) << 3));
                    vg[j] = *(const float4*)(Gsrc + (size_t)(ia >> 4) * DM + kt + ((ia & 15) << 2));
                    vu[j] = *(const float4*)(Usrc + (size_t)(ia >> 4) * DM + kt + ((ia & 15) << 2));
                }
            }
        }
    }
}

// ===========================================================================
// DN kernels (warp-specialized), CTA 128Mx128N
// ===========================================================================
__global__ __launch_bounds__(512)
void k_sh_dn(const float* __restrict__ sdw, float* __restrict__ out)
{
    extern __shared__ char sm[];
    const int tid = threadIdx.x, wid = tid >> 5, lane = tid & 31;
    const int t0 = blockIdx.x * 128, d0 = blockIdx.y * 128;
    uint32_t smb = smem_u32(sm);
    const int NIT = 64;

    if (wid < 8) {
        const int wm = (wid >> 1) * 32, wn = (wid & 1) * 64;
        const uint32_t offA0 = (uint32_t)(wm + (lane & 15)) * SST_B + (lane >> 4) * 16;
        const uint32_t offA1 = offA0 + 16 * SST_B;
        const uint32_t offB  = (uint32_t)(wn + ((lane >> 4) << 3) + (lane & 7)) * SST_B
                             + ((lane >> 3) & 1) * 16;
        float ac[2][8][4] = {};
        for (int it = 0; it < NIT; it++) {
            int st = it % S_STAGES;
            BAR_SYNC(1 + st);
            dn_cons(smb + st * DN_STG, offA0, offA1, offB, ac);
            BAR_ARRIVE(4 + st);
        }
        const int rl = lane >> 2, cp2 = (lane & 3) * 2;
#pragma unroll
        for (int mf = 0; mf < 2; mf++)
#pragma unroll
            for (int nf = 0; nf < 8; nf++) {
                int row = t0 + wm + mf * 16 + rl;
                int col = d0 + wn + nf * 8 + cp2;
                float* b0 = out + (size_t)row * DM + col;
                *(float2*)b0 = make_float2(ac[mf][nf][0], ac[mf][nf][1]);
                *(float2*)(b0 + (size_t)8 * DM) = make_float2(ac[mf][nf][2], ac[mf][nf][3]);
            }
    } else {
        const int ptid = tid - 256;
        uint4 va[4]; float4 vb[8];
#pragma unroll
        for (int j = 0; j < 4; j++) {
            int ia = ptid + j * 256;
            va[j] = *(const uint4*)(g_hs + ((size_t)t0 + (ia >> 3)) * SFF + ((ia & 7) << 3));
        }
#pragma unroll
        for (int j = 0; j < 8; j++) {
            int ib = ptid + j * 256;
            vb[j] = *(const float4*)(sdw + ((size_t)d0 + (ib >> 4)) * SFF + ((ib & 15) << 2));
        }
        for (int it = 0; it < NIT; it++) {
            int st = it % S_STAGES;
            if (it >= S_STAGES) BAR_SYNC(4 + st);
            char* base = sm + st * DN_STG;
            char* A = base; char* B = base + ABYTES;
#pragma unroll
            for (int j = 0; j < 4; j++) {
                int ia = ptid + j * 256;
                copy_storeA(va[j], A, ia >> 3, (ia & 7) << 3);
            }
#pragma unroll
            for (int j = 0; j < 8; j++) {
                int ib = ptid + j * 256;
                cvt_storeBh(vb[j], B, ib >> 4, (ib & 15) << 2);
            }
            BAR_ARRIVE(1 + st);
            if (it + 1 < NIT) {
                int s2 = (it + 1) >> 5;
                int kt = ((it + 1) & 31) * 64;
#pragma unroll
                for (int j = 0; j < 4; j++) {
                    int ia = ptid + j * 256;
                    va[j] = *(const uint4*)(g_hs + ((size_t)s2 * NT + t0 + (ia >> 3)) * SFF + kt + ((ia & 7) << 3));
                }
#pragma unroll
                for (int j = 0; j < 8; j++) {
                    int ib = ptid + j * 256;
                    vb[j] = *(const float4*)(sdw + ((size_t)s2 * DM + d0 + (ib >> 4)) * SFF + kt + ((ib & 15) << 2));
                }
            }
        }
    }
}

// ---- expert down fused with weighted combine (atomicAdd onto out) ---------
__global__ __launch_bounds__(512)
void k_ex_dn(const float* __restrict__ dw, float* __restrict__ out)
{
    const int e = blockIdx.x;
    const int t0 = blockIdx.y * 128, d0 = blockIdx.z * 128;
    if (t0 >= g_counts[e]) return;

    extern __shared__ char sm[];
    const int tid = threadIdx.x, wid = tid >> 5, lane = tid & 31;
    uint32_t smb = smem_u32(sm);
    const int NIT = FF / 64;

    if (wid < 8) {
        const int wm = (wid >> 1) * 32, wn = (wid & 1) * 64;
        const uint32_t offA0 = (uint32_t)(wm + (lane & 15)) * SST_B + (lane >> 4) * 16;
        const uint32_t offA1 = offA0 + 16 * SST_B;
        const uint32_t offB  = (uint32_t)(wn + ((lane >> 4) << 3) + (lane & 7)) * SST_B
                             + ((lane >> 3) & 1) * 16;
        float ac[2][8][4] = {};
        for (int it = 0; it < NIT; it++) {
            int st = it % S_STAGES;
            BAR_SYNC(1 + st);
            dn_cons(smb + st * DN_STG, offA0, offA1, offB, ac);
            BAR_ARRIVE(4 + st);
        }
        const int rl = lane >> 2, cp2 = (lane & 3) * 2;
#pragma unroll
        for (int mf = 0; mf < 2; mf++) {
            int s0i = t0 + wm + mf * 16 + rl;
            int s1i = s0i + 8;
            float w0 = g_w_slot[e * CAP + s0i];
            float w1 = g_w_slot[e * CAP + s1i];
            int   k0 = g_tok_table[e * CAP + s0i];
            int   k1 = g_tok_table[e * CAP + s1i];
#pragma unroll
            for (int nf = 0; nf < 8; nf++) {
                int col = d0 + wn + nf * 8 + cp2;
                if (w0 != 0.f) {
                    float* p = out + (size_t)k0 * DM + col;
                    atomicAdd(p,     w0 * ac[mf][nf][0]);
                    atomicAdd(p + 1, w0 * ac[mf][nf][1]);
                }
                if (w1 != 0.f) {
                    float* p = out + (size_t)k1 * DM + col;
                    atomicAdd(p,     w1 * ac[mf][nf][2]);
                    atomicAdd(p + 1, w1 * ac[mf][nf][3]);
                }
            }
        }
    } else {
        const int ptid = tid - 256;
        const __half* Asrc = g_h + ((size_t)e * CAP + t0) * FF;
        const float*  Bsrc = dw  + ((size_t)e * DM + d0) * FF;
        uint4 va[4]; float4 vb[8];
#pragma unroll
        for (int j = 0; j < 4; j++) {
            int ia = ptid + j * 256;
            va[j] = *(const uint4*)(Asrc + (size_t)(ia >> 3) * FF + ((ia & 7) << 3));
        }
#pragma unroll
        for (int j = 0; j < 8; j++) {
            int ib = ptid + j * 256;
            vb[j] = *(const float4*)(Bsrc + (size_t)(ib >> 4) * FF + ((ib & 15) << 2));
        }
        for (int it = 0; it < NIT; it++) {
            int st = it % S_STAGES;
            if (it >= S_STAGES) BAR_SYNC(4 + st);
            char* base = sm + st * DN_STG;
            char* A = base; char* B = base + ABYTES;
#pragma unroll
            for (int j = 0; j < 4; j++) {
                int ia = ptid + j * 256;
                copy_storeA(va[j], A, ia >> 3, (ia & 7) << 3);
            }
#pragma unroll
            for (int j = 0; j < 8; j++) {
                int ib = ptid + j * 256;
                cvt_storeBh(vb[j], B, ib >> 4, (ib & 15) << 2);
            }
            BAR_ARRIVE(1 + st);
            if (it + 1 < NIT) {
                int kt = (it + 1) * 64;
#pragma unroll
                for (int j = 0; j < 4; j++) {
                    int ia = ptid + j * 256;
                    va[j] = *(const uint4*)(Asrc + (size_t)(ia >> 3) * FF + kt + ((ia & 7) << 3));
                }
#pragma unroll
                for (int j = 0; j < 8; j++) {
                    int ib = ptid + j * 256;
                    vb[j] = *(const float4*)(Bsrc + (size_t)(ib >> 4) * FF + kt + ((ib & 15) << 2));
                }
            }
        }
    }
}

// ===========================================================================
// Launch
// ===========================================================================
extern "C" void kernel_launch(void* const* d_in, const int* in_sizes, int n_in,
                              void* d_out, int out_size)
{
    const float* x      = (const float*)d_in[0];
    const float* rw     = (const float*)d_in[1];
    const float* rbias  = (const float*)d_in[2];
    const float* gate_w = (const float*)d_in[3];
    const float* up_w   = (const float*)d_in[4];
    const float* down_w = (const float*)d_in[5];
    const float* sg_w   = (const float*)d_in[6];
    const float* su_w   = (const float*)d_in[7];
    const float* sd_w   = (const float*)d_in[8];
    float* out = (float*)d_out;

    cudaFuncSetAttribute(k_sh_gu, cudaFuncAttributeMaxDynamicSharedMemorySize, GU_SMEM);
    cudaFuncSetAttribute(k_ex_gu, cudaFuncAttributeMaxDynamicSharedMemorySize, GU_SMEM);
    cudaFuncSetAttribute(k_sh_dn, cudaFuncAttributeMaxDynamicSharedMemorySize, DN_SMEM);
    cudaFuncSetAttribute(k_ex_dn, cudaFuncAttributeMaxDynamicSharedMemorySize, DN_SMEM);

    k_cvt_x<<<NT * DM / 1024, 256>>>(x);
    k_router_logits<<<NT / RBM, 256>>>(x, rw);
    k_topk<<<NT, 32>>>(rbias);
    k_dispatch_atomic<<<NP / 256, 256>>>();
    k_tail_fill<<<NE, 256>>>();

    k_ex_gu<<<dim3(NE, CAP / 128, FF / 64), 512, GU_SMEM>>>(gate_w, up_w);
    k_sh_gu<<<dim3(NT / 128, SFF / 64, NS), 512, GU_SMEM>>>(sg_w, su_w);

    k_sh_dn<<<dim3(NT / 128, DM / 128), 512, DN_SMEM>>>(sd_w, out);
    // accumulates onto k_sh_dn's output; same stream => ordered
    k_ex_dn<<<dim3(NE, CAP / 128, DM / 128), 512, DN_SMEM>>>(down_w, out);
}

// round 12
// speedup vs baseline: 1.1501x; 1.0035x over previous
#include <cuda_runtime.h>
#include <cuda_fp16.h>
#include <math.h>
#include <stdint.h>

// ---------------------------------------------------------------------------
// Problem constants
// ---------------------------------------------------------------------------
#define NT   2048
#define DM   2048
#define NE   64
#define TOPK 4
#define FF   512
#define NS   2
#define SFF  2048
#define CAP  256
#define NP   (NT * TOPK)

// ---------------------------------------------------------------------------
// Device scratch
// ---------------------------------------------------------------------------
__device__ float  g_logits[NT * NE];
__device__ int    g_tok_table[NE * CAP];
__device__ float  g_w_slot[NE * CAP];
__device__ int    g_counts[NE];
__device__ __half g_xh[NT * DM];
__device__ __half g_h [NE * CAP * FF];
__device__ __half g_hs[NS * NT * SFF];

// ---------------------------------------------------------------------------
// Helpers
// ---------------------------------------------------------------------------
__device__ __forceinline__ uint32_t smem_u32(const void* p) {
    uint32_t a;
    asm("{ .reg .u64 t; cvta.to.shared.u64 t, %1; cvt.u32.u64 %0, t; }" : "=r"(a) : "l"(p));
    return a;
}
__device__ __forceinline__ void ldsm4(uint32_t r[4], uint32_t a) {
    asm volatile("ldmatrix.sync.aligned.m8n8.x4.shared.b16 {%0,%1,%2,%3}, [%4];"
        : "=r"(r[0]), "=r"(r[1]), "=r"(r[2]), "=r"(r[3]) : "r"(a));
}
__device__ __forceinline__ void mma_f16(float c[4], const uint32_t a[4], const uint32_t b[2]) {
    asm volatile("mma.sync.aligned.m16n8k16.row.col.f32.f16.f16.f32 "
        "{%0,%1,%2,%3}, {%4,%5,%6,%7}, {%8,%9}, {%0,%1,%2,%3};"
        : "+f"(c[0]), "+f"(c[1]), "+f"(c[2]), "+f"(c[3])
        : "r"(a[0]), "r"(a[1]), "r"(a[2]), "r"(a[3]), "r"(b[0]), "r"(b[1]));
}
__device__ __forceinline__ uint32_t h2u(__half2 h) { return *(uint32_t*)&h; }

#define SST_B 144

__device__ __forceinline__ void cvt_storeBh(float4 v, char* hi, int r, int c4) {
    __half2 h0 = __floats2half2_rn(v.x, v.y);
    __half2 h1 = __floats2half2_rn(v.z, v.w);
    *(uint2*)(hi + (uint32_t)(r * SST_B + c4 * 2)) = make_uint2(h2u(h0), h2u(h1));
}
__device__ __forceinline__ float silu_f(float g) { return g / (1.f + expf(-g)); }

// Stage layouts (3-stage ring)
#define ABYTES 18432
#define BBYTES  9216
#define GU_STG (ABYTES + 2 * BBYTES)     // 36864
#define DN_STG (2 * ABYTES)              // 36864
#define S_STAGES 3
#define GU_SMEM (S_STAGES * GU_STG)
#define DN_SMEM (S_STAGES * DN_STG)

#define BAR_SYNC(id)   asm volatile("bar.sync %0, 512;"   :: "r"(id) : "memory")
#define BAR_ARRIVE(id) asm volatile("bar.arrive %0, 512;" :: "r"(id) : "memory")

// ===========================================================================
// 0) x -> fp16, zero counts/tables/out (grid = NT*DM/1024 = 4096 blocks)
// ===========================================================================
__global__ __launch_bounds__(256)
void k_cvt_x(const float* __restrict__ x, float* __restrict__ out)
{
    int gtid = blockIdx.x * 256 + threadIdx.x;
    if (blockIdx.x == 0 && threadIdx.x < NE) g_counts[threadIdx.x] = 0;
    if (gtid < NE * CAP) {
        g_tok_table[gtid] = 0;
        g_w_slot[gtid]    = 0.f;
    }
    int i = gtid * 4;
    float4 v = *(const float4*)(x + i);
    __half2 h0 = __floats2half2_rn(v.x, v.y);
    __half2 h1 = __floats2half2_rn(v.z, v.w);
    *(uint2*)(g_xh + i) = make_uint2(h2u(h0), h2u(h1));
    *(float4*)(out + i) = make_float4(0.f, 0.f, 0.f, 0.f);
}

// ===========================================================================
// 1) Router logits (SIMT fp32)
// ===========================================================================
#define RBM 64
#define RBK 16
__global__ __launch_bounds__(256)
void k_router_logits(const float* __restrict__ x, const float* __restrict__ rw)
{
    __shared__ __align__(16) float As[RBK][RBM];
    __shared__ __align__(16) float Bs[RBK][RBM];
    const int tid = threadIdx.x;
    const int t0  = blockIdx.x * RBM;
    const int lr  = tid >> 2, lk = (tid & 3) * 4;
    const int ty4 = (tid >> 4) * 4, tx4 = (tid & 15) * 4;
    float acc[4][4];
#pragma unroll
    for (int i = 0; i < 4; i++)
#pragma unroll
        for (int j = 0; j < 4; j++) acc[i][j] = 0.f;
    for (int kt = 0; kt < DM; kt += RBK) {
        float4 a = *(const float4*)(x + (size_t)(t0 + lr) * DM + kt + lk);
        As[lk+0][lr] = a.x; As[lk+1][lr] = a.y; As[lk+2][lr] = a.z; As[lk+3][lr] = a.w;
        float4 b = *(const float4*)(rw + (size_t)lr * DM + kt + lk);
        Bs[lk+0][lr] = b.x; Bs[lk+1][lr] = b.y; Bs[lk+2][lr] = b.z; Bs[lk+3][lr] = b.w;
        __syncthreads();
#pragma unroll
        for (int k = 0; k < RBK; k++) {
            float4 av = *(const float4*)&As[k][ty4];
            float4 bv = *(const float4*)&Bs[k][tx4];
            float a4[4] = {av.x, av.y, av.z, av.w};
            float b4[4] = {bv.x, bv.y, bv.z, bv.w};
#pragma unroll
            for (int i = 0; i < 4; i++)
#pragma unroll
                for (int j = 0; j < 4; j++) acc[i][j] += a4[i] * b4[j];
        }
        __syncthreads();
    }
#pragma unroll
    for (int i = 0; i < 4; i++)
#pragma unroll
        for (int j = 0; j < 4; j++)
            g_logits[(size_t)(t0 + ty4 + i) * NE + tx4 + j] = acc[i][j];
}

// ===========================================================================
// 2) Top-k + dispatch fused (1 warp / token; lane 0 inserts the 4 pairs)
// ===========================================================================
__global__ void k_topk_dispatch(const float* __restrict__ bias)
{
    const int n = blockIdx.x, lane = threadIdx.x;
    float l0 = g_logits[n * NE + lane];
    float l1 = g_logits[n * NE + 32 + lane];
    float s0 = l0 + bias[lane];
    float s1 = l1 + bias[32 + lane];
    int ch_idx[TOPK]; float ch_l[TOPK];
#pragma unroll
    for (int r = 0; r < TOPK; r++) {
        float v = s0; int idx = lane;
        if (s1 > v) { v = s1; idx = lane + 32; }
#pragma unroll
        for (int off = 16; off > 0; off >>= 1) {
            float ov = __shfl_xor_sync(0xffffffffu, v, off);
            int   oi = __shfl_xor_sync(0xffffffffu, idx, off);
            if (ov > v || (ov == v && oi < idx)) { v = ov; idx = oi; }
        }
        int owner = (idx < 32) ? idx : (idx - 32);
        float rawA = __shfl_sync(0xffffffffu, l0, owner);
        float rawB = __shfl_sync(0xffffffffu, l1, owner);
        ch_idx[r] = idx;
        ch_l[r]   = (idx < 32) ? rawA : rawB;
        if (lane == owner) { if (idx < 32) s0 = -INFINITY; else s1 = -INFINITY; }
    }
    if (lane == 0) {
        float m = ch_l[0];
#pragma unroll
        for (int r = 1; r < TOPK; r++) m = fmaxf(m, ch_l[r]);
        float w[TOPK], sum = 0.f;
#pragma unroll
        for (int r = 0; r < TOPK; r++) { w[r] = expf(ch_l[r] - m); sum += w[r]; }
        float inv = 1.f / sum;
#pragma unroll
        for (int r = 0; r < TOPK; r++) {
            int e = ch_idx[r];
            int slot = atomicAdd(&g_counts[e], 1);
            if (slot < CAP) {
                g_tok_table[e * CAP + slot] = n;
                g_w_slot[e * CAP + slot]    = w[r] * inv;
            }
        }
    }
}

// ===========================================================================
// Consumer compute cores
// ===========================================================================
__device__ __forceinline__ void gu_cons(uint32_t ub,
    uint32_t offA0, uint32_t offA1, uint32_t offB,
    float ag[2][4][4], float au[2][4][4])
{
    const uint32_t uA = ub, uBg = ub + ABYTES, uBu = uBg + BBYTES;
#pragma unroll
    for (int ks = 0; ks < 4; ks++) {
        uint32_t kb = ks * 32;
        uint32_t ah[2][4], bg[8], bu[8];
        ldsm4(ah[0], uA + offA0 + kb); ldsm4(ah[1], uA + offA1 + kb);
        ldsm4(bg,     uBg + offB + kb); ldsm4(bg + 4, uBg + offB + 16 * SST_B + kb);
        ldsm4(bu,     uBu + offB + kb); ldsm4(bu + 4, uBu + offB + 16 * SST_B + kb);
#pragma unroll
        for (int mf = 0; mf < 2; mf++)
#pragma unroll
            for (int nf = 0; nf < 4; nf++) {
                mma_f16(ag[mf][nf], ah[mf], &bg[nf * 2]);
                mma_f16(au[mf][nf], ah[mf], &bu[nf * 2]);
            }
    }
}

__device__ __forceinline__ void dn_cons(uint32_t ub,
    uint32_t offA0, uint32_t offA1, uint32_t offB,
    float ac[2][8][4])
{
    const uint32_t uA = ub, uB = ub + ABYTES;
#pragma unroll
    for (int ks = 0; ks < 4; ks++) {
        uint32_t kb = ks * 32;
        uint32_t ah[2][4], bh[16];
        ldsm4(ah[0], uA + offA0 + kb); ldsm4(ah[1], uA + offA1 + kb);
#pragma unroll
        for (int q = 0; q < 4; q++)
            ldsm4(bh + 4 * q, uB + offB + q * 16 * SST_B + kb);
#pragma unroll
        for (int mf = 0; mf < 2; mf++)
#pragma unroll
            for (int nf = 0; nf < 8; nf++)
                mma_f16(ac[mf][nf], ah[mf], &bh[nf * 2]);
    }
}

// ===========================================================================
// Merged GU kernel: linear grid [0, 2048)
//   idx < 1024 : expert GU   e=idx>>4, t0=((idx>>3)&1)*128, f0=(idx&7)*64
//   idx >= 1024: shared GU   j=idx-1024: t0=(j&15)*128, f0=((j>>4)&31)*64, s=j>>9
// ===========================================================================
__global__ __launch_bounds__(512)
void k_gu(const float* __restrict__ gw,  const float* __restrict__ uw,
          const float* __restrict__ sgw, const float* __restrict__ suw)
{
    extern __shared__ char sm[];
    __shared__ int toks[128];
    const int tid = threadIdx.x, wid = tid >> 5, lane = tid & 31;
    uint32_t smb = smem_u32(sm);
    const int NIT = DM / 64;
    const int idx = blockIdx.x;

    const bool is_ex = (idx < 1024);
    int e = 0, t0, f0, s = 0;
    const float *Gw, *Uw;
    if (is_ex) {
        e  = idx >> 4;
        t0 = ((idx >> 3) & 1) * 128;
        f0 = (idx & 7) * 64;
        if (t0 >= g_counts[e]) return;
        Gw = gw + ((size_t)e * FF + f0) * DM;
        Uw = uw + ((size_t)e * FF + f0) * DM;
        if (tid < 128) toks[tid] = g_tok_table[e * CAP + t0 + tid];
        __syncthreads();
    } else {
        int j = idx - 1024;
        t0 = (j & 15) * 128;
        f0 = ((j >> 4) & 31) * 64;
        s  = j >> 9;
        Gw = sgw + ((size_t)s * SFF + f0) * DM;
        Uw = suw + ((size_t)s * SFF + f0) * DM;
    }

    if (wid < 8) {
        const int wm = (wid >> 1) * 32, wn = (wid & 1) * 32;
        const uint32_t offA0 = (uint32_t)(wm + (lane & 15)) * SST_B + (lane >> 4) * 16;
        const uint32_t offA1 = offA0 + 16 * SST_B;
        const uint32_t offB  = (uint32_t)(wn + ((lane >> 4) << 3) + (lane & 7)) * SST_B
                             + ((lane >> 3) & 1) * 16;
        float ag[2][4][4] = {}, au[2][4][4] = {};
        for (int it = 0; it < NIT; it++) {
            int st = it % S_STAGES;
            BAR_SYNC(1 + st);
            gu_cons(smb + st * GU_STG, offA0, offA1, offB, ag, au);
            BAR_ARRIVE(4 + st);
        }
        const int rl = lane >> 2, cp2 = (lane & 3) * 2;
#pragma unroll
        for (int mf = 0; mf < 2; mf++)
#pragma unroll
            for (int nf = 0; nf < 4; nf++) {
                int row = t0 + wm + mf * 16 + rl;
                int col = f0 + wn + nf * 8 + cp2;
                __half2 v0 = __floats2half2_rn(silu_f(ag[mf][nf][0]) * au[mf][nf][0],
                                               silu_f(ag[mf][nf][1]) * au[mf][nf][1]);
                __half2 v1 = __floats2half2_rn(silu_f(ag[mf][nf][2]) * au[mf][nf][2],
                                               silu_f(ag[mf][nf][3]) * au[mf][nf][3]);
                if (is_ex) {
                    __half* b0 = g_h + ((size_t)e * CAP + row) * FF + col;
                    *(__half2*)b0 = v0;
                    *(__half2*)(b0 + (size_t)8 * FF) = v1;
                } else {
                    __half* b0 = g_hs + ((size_t)s * NT + row) * SFF + col;
                    *(__half2*)b0 = v0;
                    *(__half2*)(b0 + (size_t)8 * SFF) = v1;
                }
            }
    } else {
        const int ptid = tid - 256;
        const __half* Axb = is_ex ? (const __half*)nullptr : g_xh + (size_t)t0 * DM;
        const __half* agp[4]; int ac8[4]; uint32_t asmo[4];
#pragma unroll
        for (int j = 0; j < 4; j++) {
            int ia = ptid + j * 256;
            int arow = ia >> 3; ac8[j] = (ia & 7) << 3;
            asmo[j] = (uint32_t)(arow * SST_B + ac8[j] * 2);
            agp[j] = is_ex ? g_xh + (size_t)toks[arow] * DM
                           : Axb + (size_t)arow * DM;
        }
        uint4 va[4]; float4 vg[4], vu[4];
#pragma unroll
        for (int j = 0; j < 4; j++) {
            int ia = ptid + j * 256;
            va[j] = *(const uint4*)(agp[j] + ac8[j]);
            vg[j] = *(const float4*)(Gw + (size_t)(ia >> 4) * DM + ((ia & 15) << 2));
            vu[j] = *(const float4*)(Uw + (size_t)(ia >> 4) * DM + ((ia & 15) << 2));
        }
        for (int it = 0; it < NIT; it++) {
            int st = it % S_STAGES;
            if (it >= S_STAGES) BAR_SYNC(4 + st);
            char* base = sm + st * GU_STG;
            char* A = base; char* Bg = base + ABYTES; char* Bu = Bg + BBYTES;
#pragma unroll
            for (int j = 0; j < 4; j++) {
                int ia = ptid + j * 256;
                *(uint4*)(A + asmo[j]) = va[j];
                cvt_storeBh(vg[j], Bg, ia >> 4, (ia & 15) << 2);
                cvt_storeBh(vu[j], Bu, ia >> 4, (ia & 15) << 2);
            }
            BAR_ARRIVE(1 + st);
            if (it + 1 < NIT) {
                int kt = (it + 1) * 64;
#pragma unroll
                for (int j = 0; j < 4; j++) {
                    int ia = ptid + j * 256;
                    va[j] = *(const uint4*)(agp[j] + kt + ac8[j]);
                    vg[j] = *(const float4*)(Gw + (size_t)(ia >> 4) * DM + kt + ((ia & 15) << 2));
                    vu[j] = *(const float4*)(Uw + (size_t)(ia >> 4) * DM + kt + ((ia & 15) << 2));
                }
            }
        }
    }
}

// ===========================================================================
// Merged DN kernel: linear grid [0, 2304). out pre-zeroed; all atomicAdd.
//   idx < 256 : shared DN  t0=(idx&15)*128, d0=(idx>>4)*128, NIT=64
//   idx >= 256: expert DN  j=idx-256: e=j>>5, t0=((j>>4)&1)*128, d0=(j&15)*128, NIT=8
// ===========================================================================
__global__ __launch_bounds__(512)
void k_dn(const float* __restrict__ sdw, const float* __restrict__ dw,
          float* __restrict__ out)
{
    extern __shared__ char sm[];
    const int tid = threadIdx.x, wid = tid >> 5, lane = tid & 31;
    uint32_t smb = smem_u32(sm);
    const int idx = blockIdx.x;

    const bool is_sh = (idx < 256);
    int e = 0, t0, d0, NIT;
    if (is_sh) {
        t0 = (idx & 15) * 128; d0 = (idx >> 4) * 128; NIT = 64;
    } else {
        int j = idx - 256;
        e = j >> 5; t0 = ((j >> 4) & 1) * 128; d0 = (j & 15) * 128; NIT = FF / 64;
        if (t0 >= g_counts[e]) return;
    }

    if (wid < 8) {
        const int wm = (wid >> 1) * 32, wn = (wid & 1) * 64;
        const uint32_t offA0 = (uint32_t)(wm + (lane & 15)) * SST_B + (lane >> 4) * 16;
        const uint32_t offA1 = offA0 + 16 * SST_B;
        const uint32_t offB  = (uint32_t)(wn + ((lane >> 4) << 3) + (lane & 7)) * SST_B
                             + ((lane >> 3) & 1) * 16;
        float ac[2][8][4] = {};
        for (int it = 0; it < NIT; it++) {
            int st = it % S_STAGES;
            BAR_SYNC(1 + st);
            dn_cons(smb + st * DN_STG, offA0, offA1, offB, ac);
            BAR_ARRIVE(4 + st);
        }
        const int rl = lane >> 2, cp2 = (lane & 3) * 2;
        if (is_sh) {
#pragma unroll
            for (int mf = 0; mf < 2; mf++)
#pragma unroll
                for (int nf = 0; nf < 8; nf++) {
                    int row = t0 + wm + mf * 16 + rl;
                    int col = d0 + wn + nf * 8 + cp2;
                    float* b0 = out + (size_t)row * DM + col;
                    atomicAdd(b0,     ac[mf][nf][0]);
                    atomicAdd(b0 + 1, ac[mf][nf][1]);
                    atomicAdd(b0 + (size_t)8 * DM,     ac[mf][nf][2]);
                    atomicAdd(b0 + (size_t)8 * DM + 1, ac[mf][nf][3]);
                }
        } else {
#pragma unroll
            for (int mf = 0; mf < 2; mf++) {
                int s0i = t0 + wm + mf * 16 + rl;
                int s1i = s0i + 8;
                float w0 = g_w_slot[e * CAP + s0i];
                float w1 = g_w_slot[e * CAP + s1i];
                int   k0 = g_tok_table[e * CAP + s0i];
                int   k1 = g_tok_table[e * CAP + s1i];
#pragma unroll
                for (int nf = 0; nf < 8; nf++) {
                    int col = d0 + wn + nf * 8 + cp2;
                    if (w0 != 0.f) {
                        float* p = out + (size_t)k0 * DM + col;
                        atomicAdd(p,     w0 * ac[mf][nf][0]);
                        atomicAdd(p + 1, w0 * ac[mf][nf][1]);
                    }
                    if (w1 != 0.f) {
                        float* p = out + (size_t)k1 * DM + col;
                        atomicAdd(p,     w1 * ac[mf][nf][2]);
                        atomicAdd(p + 1, w1 * ac[mf][nf][3]);
                    }
                }
            }
        }
    } else {
        const int ptid = tid - 256;
        int arow[4], ac8[4]; uint32_t asmo[4];
#pragma unroll
        for (int j = 0; j < 4; j++) {
            int ia = ptid + j * 256;
            arow[j] = ia >> 3; ac8[j] = (ia & 7) << 3;
            asmo[j] = (uint32_t)(arow[j] * SST_B + ac8[j] * 2);
        }
        const __half* Aex = g_h + ((size_t)e * CAP + t0) * FF;
        const float*  Bex = dw  + ((size_t)e * DM + d0) * FF;
        uint4 va[4]; float4 vb[8];
        if (is_sh) {
#pragma unroll
            for (int j = 0; j < 4; j++)
                va[j] = *(const uint4*)(g_hs + ((size_t)t0 + arow[j]) * SFF + ac8[j]);
#pragma unroll
            for (int j = 0; j < 8; j++) {
                int ib = ptid + j * 256;
                vb[j] = *(const float4*)(sdw + ((size_t)d0 + (ib >> 4)) * SFF + ((ib & 15) << 2));
            }
        } else {
#pragma unroll
            for (int j = 0; j < 4; j++)
                va[j] = *(const uint4*)(Aex + (size_t)arow[j] * FF + ac8[j]);
#pragma unroll
            for (int j = 0; j < 8; j++) {
                int ib = ptid + j * 256;
                vb[j] = *(const float4*)(Bex + (size_t)(ib >> 4) * FF + ((ib & 15) << 2));
            }
        }
        for (int it = 0; it < NIT; it++) {
            int st = it % S_STAGES;
            if (it >= S_STAGES) BAR_SYNC(4 + st);
            char* base = sm + st * DN_STG;
            char* A = base; char* B = base + ABYTES;
#pragma unroll
            for (int j = 0; j < 4; j++)
                *(uint4*)(A + asmo[j]) = va[j];
#pragma unroll
            for (int j = 0; j < 8; j++) {
                int ib = ptid + j * 256;
                cvt_storeBh(vb[j], B, ib >> 4, (ib & 15) << 2);
            }
            BAR_ARRIVE(1 + st);
            if (it + 1 < NIT) {
                if (is_sh) {
                    int s2 = (it + 1) >> 5, kt = ((it + 1) & 31) * 64;
#pragma unroll
                    for (int j = 0; j < 4; j++)
                        va[j] = *(const uint4*)(g_hs + ((size_t)s2 * NT + t0 + arow[j]) * SFF + kt + ac8[j]);
#pragma unroll
                    for (int j = 0; j < 8; j++) {
                        int ib = ptid + j * 256;
                        vb[j] = *(const float4*)(sdw + ((size_t)s2 * DM + d0 + (ib >> 4)) * SFF + kt + ((ib & 15) << 2));
                    }
                } else {
                    int kt = (it + 1) * 64;
#pragma unroll
                    for (int j = 0; j < 4; j++)
                        va[j] = *(const uint4*)(Aex + (size_t)arow[j] * FF + kt + ac8[j]);
#pragma unroll
                    for (int j = 0; j < 8; j++) {
                        int ib = ptid + j * 256;
                        vb[j] = *(const float4*)(Bex + (size_t)(ib >> 4) * FF + kt + ((ib & 15) << 2));
                    }
                }
            }
        }
    }
}

// ===========================================================================
// Launch
// ===========================================================================
extern "C" void kernel_launch(void* const* d_in, const int* in_sizes, int n_in,
                              void* d_out, int out_size)
{
    const float* x      = (const float*)d_in[0];
    const float* rw     = (const float*)d_in[1];
    const float* rbias  = (const float*)d_in[2];
    const float* gate_w = (const float*)d_in[3];
    const float* up_w   = (const float*)d_in[4];
    const float* down_w = (const float*)d_in[5];
    const float* sg_w   = (const float*)d_in[6];
    const float* su_w   = (const float*)d_in[7];
    const float* sd_w   = (const float*)d_in[8];
    float* out = (float*)d_out;

    cudaFuncSetAttribute(k_gu, cudaFuncAttributeMaxDynamicSharedMemorySize, GU_SMEM);
    cudaFuncSetAttribute(k_dn, cudaFuncAttributeMaxDynamicSharedMemorySize, DN_SMEM);

    k_cvt_x<<<NT * DM / 1024, 256>>>(x, out);
    k_router_logits<<<NT / RBM, 256>>>(x, rw);
    k_topk_dispatch<<<NT, 32>>>(rbias);

    k_gu<<<2048, 512, GU_SMEM>>>(gate_w, up_w, sg_w, su_w);
    k_dn<<<2304, 512, DN_SMEM>>>(sd_w, down_w, out);
}